// round 1
// baseline (speedup 1.0000x reference)
#include <cuda_runtime.h>
#include <math.h>
#include <stdint.h>

// Problem constants
#define BB 4
#define LL 2048
#define DM 1024
#define DS 64
#define DI 2048
#define MROWS (BB*LL)        // 8192
#define N1 (2*DI)            // 4096
#define N2 (2*DS + DI)       // 2176

// ---------------- scratch (device globals; no allocations allowed) -------------
__device__ float g_xs  [(size_t)MROWS*DI];   // silu(xs)
__device__ float g_sres[(size_t)MROWS*DI];   // silu(res)
__device__ float g_draw[(size_t)MROWS*DS];
__device__ float g_Bsel[(size_t)MROWS*DS];
__device__ float g_Csel[(size_t)MROWS*DI];
__device__ float g_delta[(size_t)MROWS*DI];
__device__ float g_y   [(size_t)MROWS*DI];
__device__ float g_z   [(size_t)MROWS*DM];
__device__ float g_Aneg[(size_t)DI*DS];

// ---------------- precompute A = -exp(A_log) ----------------------------------
__global__ void aneg_kernel(const float* __restrict__ A_log) {
    int i = blockIdx.x * blockDim.x + threadIdx.x;
    if (i < DI*DS) g_Aneg[i] = -__expf(A_log[i]);
}

// ---------------- generic fp32 SIMT GEMM with fused epilogues ------------------
// C = A(MxK) @ B(KxN) + bias, epilogue per EPI:
//   EPI=0: silu, split cols [0,DI) -> O0 (xs), [DI,2DI) -> O1 (sres)
//   EPI=1: split cols [0,DS)->O0 draw, [DS,2DS)->O1 Bsel, rest->O2 Csel
//   EPI=2: softplus -> O0
//   EPI=3: + aux (residual) -> O0
constexpr int BM = 128, BN = 128, BK = 16, TM = 8, TN = 8; // 256 threads

template<int EPI>
__global__ __launch_bounds__(256)
void gemm_kernel(const float* __restrict__ A, const float* __restrict__ B,
                 const float* __restrict__ bias, const float* __restrict__ aux,
                 float* __restrict__ O0, float* __restrict__ O1, float* __restrict__ O2,
                 int M, int N, int K)
{
    __shared__ float As[BK][BM];
    __shared__ float Bs[BK][BN];

    const int tid  = threadIdx.x;
    const int bx   = blockIdx.x;   // N tile
    const int by   = blockIdx.y;   // M tile
    const int tcol = tid & 15;     // 0..15
    const int trow = tid >> 4;     // 0..15

    const float* Ab = A + (size_t)by * BM * K;
    const float* Bb = B + (size_t)bx * BN;

    const int arow  = tid >> 2;    // 0..63
    const int acol4 = tid & 3;     // float4 slot along BK
    const int brow  = tid >> 5;    // 0..7
    const int bcol4 = tid & 31;    // float4 slot along BN

    float acc[TM][TN] = {};

    for (int k0 = 0; k0 < K; k0 += BK) {
#pragma unroll
        for (int r = 0; r < 2; ++r) {
            int row = arow + r * 64;
            float4 v = *(const float4*)(Ab + (size_t)row * K + k0 + acol4 * 4);
            As[acol4*4+0][row] = v.x;
            As[acol4*4+1][row] = v.y;
            As[acol4*4+2][row] = v.z;
            As[acol4*4+3][row] = v.w;
        }
#pragma unroll
        for (int r = 0; r < 2; ++r) {
            int row = brow + r * 8;
            float4 v = *(const float4*)(Bb + (size_t)(k0 + row) * N + bcol4 * 4);
            *(float4*)(&Bs[row][bcol4*4]) = v;
        }
        __syncthreads();

#pragma unroll
        for (int k = 0; k < BK; ++k) {
            float4 a0 = *(const float4*)(&As[k][trow*TM]);
            float4 a1 = *(const float4*)(&As[k][trow*TM+4]);
            float4 b0 = *(const float4*)(&Bs[k][tcol*TN]);
            float4 b1 = *(const float4*)(&Bs[k][tcol*TN+4]);
            float rm[TM] = {a0.x,a0.y,a0.z,a0.w,a1.x,a1.y,a1.z,a1.w};
            float rn[TN] = {b0.x,b0.y,b0.z,b0.w,b1.x,b1.y,b1.z,b1.w};
#pragma unroll
            for (int i = 0; i < TM; ++i)
#pragma unroll
                for (int j = 0; j < TN; ++j)
                    acc[i][j] = fmaf(rm[i], rn[j], acc[i][j]);
        }
        __syncthreads();
    }

#pragma unroll
    for (int i = 0; i < TM; ++i) {
        int m = by * BM + trow * TM + i;
#pragma unroll
        for (int j = 0; j < TN; ++j) {
            int n = bx * BN + tcol * TN + j;
            float v = acc[i][j] + bias[n];
            if (EPI == 0) {
                float s = v / (1.0f + __expf(-v));     // silu
                if (n < DI) O0[(size_t)m * DI + n] = s;
                else        O1[(size_t)m * DI + (n - DI)] = s;
            } else if (EPI == 1) {
                if (n < DS)          O0[(size_t)m * DS + n] = v;
                else if (n < 2*DS)   O1[(size_t)m * DS + (n - DS)] = v;
                else                 O2[(size_t)m * DI + (n - 2*DS)] = v;
            } else if (EPI == 2) {
                float sp = (v > 20.0f) ? v : log1pf(__expf(v));  // softplus
                O0[(size_t)m * N + n] = sp;
            } else {
                O0[(size_t)m * N + n] = v + aux[(size_t)m * N + n]; // +residual
            }
        }
    }
}

// ---------------- selective scan: 1 warp per (b,d) channel, 2 states/lane ------
__global__ __launch_bounds__(256)
void scan_kernel(const float* __restrict__ delta, const float* __restrict__ Bsel,
                 const float* __restrict__ xs,    const float* __restrict__ Csel,
                 const float* __restrict__ sres,  const float* __restrict__ Dp,
                 float* __restrict__ y)
{
    const int w    = (blockIdx.x * blockDim.x + threadIdx.x) >> 5;
    const int lane = threadIdx.x & 31;
    const int b = w >> 11;         // w / DI
    const int d = w & (DI - 1);

    const float A0  = g_Aneg[d * DS + lane];
    const float A1  = g_Aneg[d * DS + lane + 32];
    const float Dpd = Dp[d];

    float h0 = 0.0f, h1 = 0.0f;

    const size_t rowbase = (size_t)b * LL * DI + d;
    const float* dptr = delta + rowbase;
    const float* xptr = xs    + rowbase;
    const float* cptr = Csel  + rowbase;
    const float* rptr = sres  + rowbase;
    const float* bptr = Bsel  + (size_t)b * LL * DS + lane;
    float*       yptr = y     + rowbase;

#pragma unroll 2
    for (int t = 0; t < LL; ++t) {
        float dt = __ldg(dptr);
        float xv = __ldg(xptr);
        float cv = __ldg(cptr);
        float sr = __ldg(rptr);
        float B0 = __ldg(bptr);
        float B1 = __ldg(bptr + 32);

        float e0 = __expf(dt * A0);
        float e1 = __expf(dt * A1);
        float u  = dt * xv;
        h0 = fmaf(e0, h0, B0 * u);
        h1 = fmaf(e1, h1, B1 * u);

        float s = h0 + h1;
#pragma unroll
        for (int o = 16; o; o >>= 1) s += __shfl_xor_sync(0xffffffffu, s, o);

        if (lane == 0) *yptr = (cv * s + xv * Dpd) * sr;

        dptr += DI; xptr += DI; cptr += DI; rptr += DI; yptr += DI; bptr += DS;
    }
}

// ---------------- layernorm ----------------------------------------------------
__device__ __forceinline__ float block_sum256(float v, float* sh) {
    __syncthreads();
#pragma unroll
    for (int o = 16; o; o >>= 1) v += __shfl_xor_sync(0xffffffffu, v, o);
    const int lane = threadIdx.x & 31, wid = threadIdx.x >> 5;
    if (lane == 0) sh[wid] = v;
    __syncthreads();
    if (threadIdx.x < 32) {
        float t = (lane < 8) ? sh[lane] : 0.0f;
#pragma unroll
        for (int o = 4; o; o >>= 1) t += __shfl_xor_sync(0xffffffffu, t, o);
        if (lane == 0) sh[8] = t;
    }
    __syncthreads();
    return sh[8];
}

__global__ __launch_bounds__(256)
void ln_kernel(const float* __restrict__ z, const float* __restrict__ gamma,
               const float* __restrict__ beta, float* __restrict__ out)
{
    __shared__ float sh[16];
    const int row = blockIdx.x;
    const float4 v = ((const float4*)(z + (size_t)row * DM))[threadIdx.x];

    float s  = (v.x + v.y) + (v.z + v.w);
    float S  = block_sum256(s, sh);
    float mu = S * (1.0f / DM);

    float dx = v.x - mu, dy = v.y - mu, dz = v.z - mu, dw = v.w - mu;
    float q  = (dx*dx + dy*dy) + (dz*dz + dw*dw);
    float Q  = block_sum256(q, sh);
    float inv = rsqrtf(Q * (1.0f / DM) + 1e-5f);

    const float4 g = ((const float4*)gamma)[threadIdx.x];
    const float4 bb = ((const float4*)beta)[threadIdx.x];
    float4 o;
    o.x = dx * inv * g.x + bb.x;
    o.y = dy * inv * g.y + bb.y;
    o.z = dz * inv * g.z + bb.z;
    o.w = dw * inv * g.w + bb.w;
    ((float4*)(out + (size_t)row * DM))[threadIdx.x] = o;
}

// ---------------- launch --------------------------------------------------------
extern "C" void kernel_launch(void* const* d_in, const int* in_sizes, int n_in,
                              void* d_out, int out_size)
{
    const float* x     = (const float*)d_in[0];
    const float* Wi    = (const float*)d_in[1];
    const float* bi    = (const float*)d_in[2];
    const float* Wx    = (const float*)d_in[3];
    const float* bx    = (const float*)d_in[4];
    const float* Wdt   = (const float*)d_in[5];
    const float* bdt   = (const float*)d_in[6];
    const float* A_log = (const float*)d_in[7];
    const float* Dp    = (const float*)d_in[8];
    const float* Wo    = (const float*)d_in[9];
    const float* bo    = (const float*)d_in[10];
    const float* gamma = (const float*)d_in[11];
    const float* beta  = (const float*)d_in[12];
    float* out = (float*)d_out;

    float *xs, *sres, *draw, *Bsel, *Csel, *delta, *y, *z;
    cudaGetSymbolAddress((void**)&xs,    g_xs);
    cudaGetSymbolAddress((void**)&sres,  g_sres);
    cudaGetSymbolAddress((void**)&draw,  g_draw);
    cudaGetSymbolAddress((void**)&Bsel,  g_Bsel);
    cudaGetSymbolAddress((void**)&Csel,  g_Csel);
    cudaGetSymbolAddress((void**)&delta, g_delta);
    cudaGetSymbolAddress((void**)&y,     g_y);
    cudaGetSymbolAddress((void**)&z,     g_z);

    // A = -exp(A_log)
    aneg_kernel<<<(DI*DS + 255)/256, 256>>>(A_log);

    // GEMM1: x @ Wi + bi -> silu -> xs | sres
    gemm_kernel<0><<<dim3(N1/BN, MROWS/BM), 256>>>(x, Wi, bi, nullptr,
                                                   xs, sres, nullptr, MROWS, N1, DM);

    // GEMM2: xs @ Wx + bx -> draw | Bsel | Csel
    gemm_kernel<1><<<dim3(N2/BN, MROWS/BM), 256>>>(xs, Wx, bx, nullptr,
                                                   draw, Bsel, Csel, MROWS, N2, DI);

    // GEMM3: draw @ Wdt + bdt -> softplus -> delta
    gemm_kernel<2><<<dim3(DI/BN, MROWS/BM), 256>>>(draw, Wdt, bdt, nullptr,
                                                   delta, nullptr, nullptr, MROWS, DI, DS);

    // selective scan (fuses +xs*Dp and *silu(res))
    scan_kernel<<<(MROWS*32)/256, 256>>>(delta, Bsel, xs, Csel, sres, Dp, y);

    // GEMM4: y @ Wo + bo + residual -> z
    gemm_kernel<3><<<dim3(DM/BN, MROWS/BM), 256>>>(y, Wo, bo, x,
                                                   z, nullptr, nullptr, MROWS, DM, DI);

    // layernorm -> out
    ln_kernel<<<MROWS, 256>>>(z, gamma, beta, out);
}

// round 2
// speedup vs baseline: 1.9111x; 1.9111x over previous
#include <cuda_runtime.h>
#include <math.h>
#include <stdint.h>

// Problem constants
#define BB 4
#define LL 2048
#define DM 1024
#define DS 64
#define DI 2048
#define MROWS (BB*LL)        // 8192
#define N1 (2*DI)            // 4096
#define N2 (2*DS + DI)       // 2176

// ---------------- scratch (device globals; no allocations allowed) -------------
__device__ float g_xs  [(size_t)MROWS*DI];   // silu(xs)
__device__ float g_sres[(size_t)MROWS*DI];   // silu(res)
__device__ float g_draw[(size_t)MROWS*DS];
__device__ float g_Bsel[(size_t)MROWS*DS];
__device__ float g_Csel[(size_t)MROWS*DI];
__device__ float g_delta[(size_t)MROWS*DI];
__device__ float g_y   [(size_t)MROWS*DI];
__device__ float g_z   [(size_t)MROWS*DM];
__device__ float g_Aneg[(size_t)DI*DS];

// ---------------- precompute A = -exp(A_log) ----------------------------------
__global__ void aneg_kernel(const float* __restrict__ A_log) {
    int i = blockIdx.x * blockDim.x + threadIdx.x;
    if (i < DI*DS) g_Aneg[i] = -__expf(A_log[i]);
}

// =====================================================================
// TF32 tensor-core GEMM: CTA 128x128, 4 warps (64x64 each), BK=16,
// 4-stage cp.async pipeline. Conflict-free padded smem, no ldmatrix.
// EPI: 0 silu->split(xs|sres), 1 split(draw|Bsel|Csel), 3 +residual
// =====================================================================
#define BKT 16
#define STG 4
#define AST 20               // A smem row stride (floats): bank-perfect
#define BST 136              // B smem row stride (floats): bank-perfect
#define ASZ (128*AST)        // 2560 floats
#define BSZ (BKT*BST)        // 2176 floats
#define STAGE_F (ASZ+BSZ)    // 4736 floats
#define SMEM_TC_BYTES (STG*STAGE_F*4)   // 75776 bytes

__device__ __forceinline__ uint32_t to_tf32(float f) {
    uint32_t r;
    asm("cvt.rna.tf32.f32 %0, %1;" : "=r"(r) : "f"(f));
    return r;
}

template<int EPI>
__global__ __launch_bounds__(128)
void gemm_tc(const float* __restrict__ A, const float* __restrict__ B,
             const float* __restrict__ bias, const float* __restrict__ aux,
             float* __restrict__ O0, float* __restrict__ O1, float* __restrict__ O2,
             int M, int N, int K)
{
    extern __shared__ float smc[];
    const int tid  = threadIdx.x;
    const int lane = tid & 31;
    const int wid  = tid >> 5;
    const int wm   = wid & 1;     // warp row (2)
    const int wn   = wid >> 1;    // warp col (2)
    const int bx   = blockIdx.x, by = blockIdx.y;

    // cp.async thread mapping
    const int am  = tid >> 2;           // A row 0..31 (+32*i)
    const int ak4 = (tid & 3) * 4;      // A k offset (floats)
    const int bk  = tid >> 5;           // B row 0..3 (+4*i)
    const int bn4 = (tid & 31) * 4;     // B n offset (floats)

    const float* Ag = A + (size_t)(by * 128) * K;
    const float* Bg = B + (size_t)(bx * 128);

    auto issue = [&](int kt, int stage) {
        float* As = smc + stage * STAGE_F;
        float* Bs = As + ASZ;
        const int k0 = kt * BKT;
#pragma unroll
        for (int i = 0; i < 4; ++i) {
            int m = am + i * 32;
            const float* g = Ag + (size_t)m * K + k0 + ak4;
            uint32_t s = (uint32_t)__cvta_generic_to_shared(As + m * AST + ak4);
            asm volatile("cp.async.cg.shared.global [%0], [%1], 16;\n" :: "r"(s), "l"(g));
        }
#pragma unroll
        for (int i = 0; i < 4; ++i) {
            int k = bk + i * 4;
            const float* g = Bg + (size_t)(k0 + k) * N + bn4;
            uint32_t s = (uint32_t)__cvta_generic_to_shared(Bs + k * BST + bn4);
            asm volatile("cp.async.cg.shared.global [%0], [%1], 16;\n" :: "r"(s), "l"(g));
        }
    };

    const int KT = K / BKT;

    for (int s = 0; s < 3; ++s) {
        if (s < KT) issue(s, s);
        asm volatile("cp.async.commit_group;\n");
    }

    float acc[4][8][4];
#pragma unroll
    for (int i = 0; i < 4; ++i)
#pragma unroll
        for (int j = 0; j < 8; ++j)
#pragma unroll
            for (int q = 0; q < 4; ++q) acc[i][j][q] = 0.0f;

    for (int kt = 0; kt < KT; ++kt) {
        asm volatile("cp.async.wait_group 2;\n");
        __syncthreads();

        if (kt + 3 < KT) issue(kt + 3, (kt + 3) & 3);
        asm volatile("cp.async.commit_group;\n");

        const float* As = smc + (kt & 3) * STAGE_F;
        const float* Bs = As + ASZ;

#pragma unroll
        for (int kk = 0; kk < 2; ++kk) {
            const int k8 = kk * 8;
            uint32_t af[4][4], bf[8][2];
#pragma unroll
            for (int mf = 0; mf < 4; ++mf) {
                const int rm = wm * 64 + mf * 16 + (lane >> 2);
                const int kc = k8 + (lane & 3);
                af[mf][0] = to_tf32(As[rm * AST + kc]);
                af[mf][1] = to_tf32(As[(rm + 8) * AST + kc]);
                af[mf][2] = to_tf32(As[rm * AST + kc + 4]);
                af[mf][3] = to_tf32(As[(rm + 8) * AST + kc + 4]);
            }
#pragma unroll
            for (int nf = 0; nf < 8; ++nf) {
                const int cn = wn * 64 + nf * 8 + (lane >> 2);
                bf[nf][0] = to_tf32(Bs[(k8 + (lane & 3)) * BST + cn]);
                bf[nf][1] = to_tf32(Bs[(k8 + 4 + (lane & 3)) * BST + cn]);
            }
#pragma unroll
            for (int mf = 0; mf < 4; ++mf)
#pragma unroll
                for (int nf = 0; nf < 8; ++nf) {
                    asm volatile(
                        "mma.sync.aligned.m16n8k8.row.col.f32.tf32.tf32.f32 "
                        "{%0,%1,%2,%3}, {%4,%5,%6,%7}, {%8,%9}, {%0,%1,%2,%3};"
                        : "+f"(acc[mf][nf][0]), "+f"(acc[mf][nf][1]),
                          "+f"(acc[mf][nf][2]), "+f"(acc[mf][nf][3])
                        : "r"(af[mf][0]), "r"(af[mf][1]), "r"(af[mf][2]), "r"(af[mf][3]),
                          "r"(bf[nf][0]), "r"(bf[nf][1]));
                }
        }
        __syncthreads();
    }

    // -------- epilogue --------
#pragma unroll
    for (int mf = 0; mf < 4; ++mf) {
        const int r0 = by * 128 + wm * 64 + mf * 16 + (lane >> 2);
#pragma unroll
        for (int nf = 0; nf < 8; ++nf) {
            const int c0 = bx * 128 + wn * 64 + nf * 8 + 2 * (lane & 3);
#pragma unroll
            for (int half = 0; half < 2; ++half) {
                const int m = r0 + half * 8;
#pragma unroll
                for (int q = 0; q < 2; ++q) {
                    const int n = c0 + q;
                    float v = acc[mf][nf][half * 2 + q] + bias[n];
                    if (EPI == 0) {
                        float s = v / (1.0f + __expf(-v));
                        if (n < DI) O0[(size_t)m * DI + n] = s;
                        else        O1[(size_t)m * DI + (n - DI)] = s;
                    } else if (EPI == 1) {
                        if (n < DS)        O0[(size_t)m * DS + n] = v;
                        else if (n < 2*DS) O1[(size_t)m * DS + (n - DS)] = v;
                        else               O2[(size_t)m * DI + (n - 2*DS)] = v;
                    } else {
                        O0[(size_t)m * N + n] = v + aux[(size_t)m * N + n];
                    }
                }
            }
        }
    }
}

// ---------------- small SIMT GEMM for GEMM3 (K=64) with softplus --------------
constexpr int BM = 128, BN = 128, BK = 16, TM = 8, TN = 8; // 256 threads

__global__ __launch_bounds__(256)
void gemm_sp(const float* __restrict__ A, const float* __restrict__ B,
             const float* __restrict__ bias,
             float* __restrict__ O0, int M, int N, int K)
{
    __shared__ float As[BK][BM];
    __shared__ float Bs[BK][BN];

    const int tid  = threadIdx.x;
    const int bx   = blockIdx.x;
    const int by   = blockIdx.y;
    const int tcol = tid & 15;
    const int trow = tid >> 4;

    const float* Ab = A + (size_t)by * BM * K;
    const float* Bb = B + (size_t)bx * BN;

    const int arow  = tid >> 2;
    const int acol4 = tid & 3;
    const int brow  = tid >> 5;
    const int bcol4 = tid & 31;

    float acc[TM][TN] = {};

    for (int k0 = 0; k0 < K; k0 += BK) {
#pragma unroll
        for (int r = 0; r < 2; ++r) {
            int row = arow + r * 64;
            float4 v = *(const float4*)(Ab + (size_t)row * K + k0 + acol4 * 4);
            As[acol4*4+0][row] = v.x;
            As[acol4*4+1][row] = v.y;
            As[acol4*4+2][row] = v.z;
            As[acol4*4+3][row] = v.w;
        }
#pragma unroll
        for (int r = 0; r < 2; ++r) {
            int row = brow + r * 8;
            float4 v = *(const float4*)(Bb + (size_t)(k0 + row) * N + bcol4 * 4);
            *(float4*)(&Bs[row][bcol4*4]) = v;
        }
        __syncthreads();

#pragma unroll
        for (int k = 0; k < BK; ++k) {
            float4 a0 = *(const float4*)(&As[k][trow*TM]);
            float4 a1 = *(const float4*)(&As[k][trow*TM+4]);
            float4 b0 = *(const float4*)(&Bs[k][tcol*TN]);
            float4 b1 = *(const float4*)(&Bs[k][tcol*TN+4]);
            float rm[TM] = {a0.x,a0.y,a0.z,a0.w,a1.x,a1.y,a1.z,a1.w};
            float rn[TN] = {b0.x,b0.y,b0.z,b0.w,b1.x,b1.y,b1.z,b1.w};
#pragma unroll
            for (int i = 0; i < TM; ++i)
#pragma unroll
                for (int j = 0; j < TN; ++j)
                    acc[i][j] = fmaf(rm[i], rn[j], acc[i][j]);
        }
        __syncthreads();
    }

#pragma unroll
    for (int i = 0; i < TM; ++i) {
        int m = by * BM + trow * TM + i;
#pragma unroll
        for (int j = 0; j < TN; ++j) {
            int n = bx * BN + tcol * TN + j;
            float v = acc[i][j] + bias[n];
            float sp = (v > 20.0f) ? v : log1pf(__expf(v));
            O0[(size_t)m * N + n] = sp;
        }
    }
}

// ---------------- selective scan: 1 warp per (b,d) channel, 2 states/lane ------
__global__ __launch_bounds__(256)
void scan_kernel(const float* __restrict__ delta, const float* __restrict__ Bsel,
                 const float* __restrict__ xs,    const float* __restrict__ Csel,
                 const float* __restrict__ sres,  const float* __restrict__ Dp,
                 float* __restrict__ y)
{
    const int w    = (blockIdx.x * blockDim.x + threadIdx.x) >> 5;
    const int lane = threadIdx.x & 31;
    const int b = w >> 11;         // w / DI
    const int d = w & (DI - 1);

    const float A0  = g_Aneg[d * DS + lane];
    const float A1  = g_Aneg[d * DS + lane + 32];
    const float Dpd = Dp[d];

    float h0 = 0.0f, h1 = 0.0f;

    const size_t rowbase = (size_t)b * LL * DI + d;
    const float* dptr = delta + rowbase;
    const float* xptr = xs    + rowbase;
    const float* cptr = Csel  + rowbase;
    const float* rptr = sres  + rowbase;
    const float* bptr = Bsel  + (size_t)b * LL * DS + lane;
    float*       yptr = y     + rowbase;

#pragma unroll 2
    for (int t = 0; t < LL; ++t) {
        float dt = __ldg(dptr);
        float xv = __ldg(xptr);
        float cv = __ldg(cptr);
        float sr = __ldg(rptr);
        float B0 = __ldg(bptr);
        float B1 = __ldg(bptr + 32);

        float e0 = __expf(dt * A0);
        float e1 = __expf(dt * A1);
        float u  = dt * xv;
        h0 = fmaf(e0, h0, B0 * u);
        h1 = fmaf(e1, h1, B1 * u);

        float s = h0 + h1;
#pragma unroll
        for (int o = 16; o; o >>= 1) s += __shfl_xor_sync(0xffffffffu, s, o);

        if (lane == 0) *yptr = (cv * s + xv * Dpd) * sr;

        dptr += DI; xptr += DI; cptr += DI; rptr += DI; yptr += DI; bptr += DS;
    }
}

// ---------------- layernorm ----------------------------------------------------
__device__ __forceinline__ float block_sum256(float v, float* sh) {
    __syncthreads();
#pragma unroll
    for (int o = 16; o; o >>= 1) v += __shfl_xor_sync(0xffffffffu, v, o);
    const int lane = threadIdx.x & 31, wid = threadIdx.x >> 5;
    if (lane == 0) sh[wid] = v;
    __syncthreads();
    if (threadIdx.x < 32) {
        float t = (lane < 8) ? sh[lane] : 0.0f;
#pragma unroll
        for (int o = 4; o; o >>= 1) t += __shfl_xor_sync(0xffffffffu, t, o);
        if (lane == 0) sh[8] = t;
    }
    __syncthreads();
    return sh[8];
}

__global__ __launch_bounds__(256)
void ln_kernel(const float* __restrict__ z, const float* __restrict__ gamma,
               const float* __restrict__ beta, float* __restrict__ out)
{
    __shared__ float sh[16];
    const int row = blockIdx.x;
    const float4 v = ((const float4*)(z + (size_t)row * DM))[threadIdx.x];

    float s  = (v.x + v.y) + (v.z + v.w);
    float S  = block_sum256(s, sh);
    float mu = S * (1.0f / DM);

    float dx = v.x - mu, dy = v.y - mu, dz = v.z - mu, dw = v.w - mu;
    float q  = (dx*dx + dy*dy) + (dz*dz + dw*dw);
    float Q  = block_sum256(q, sh);
    float inv = rsqrtf(Q * (1.0f / DM) + 1e-5f);

    const float4 g = ((const float4*)gamma)[threadIdx.x];
    const float4 bb = ((const float4*)beta)[threadIdx.x];
    float4 o;
    o.x = dx * inv * g.x + bb.x;
    o.y = dy * inv * g.y + bb.y;
    o.z = dz * inv * g.z + bb.z;
    o.w = dw * inv * g.w + bb.w;
    ((float4*)(out + (size_t)row * DM))[threadIdx.x] = o;
}

// ---------------- launch --------------------------------------------------------
extern "C" void kernel_launch(void* const* d_in, const int* in_sizes, int n_in,
                              void* d_out, int out_size)
{
    const float* x     = (const float*)d_in[0];
    const float* Wi    = (const float*)d_in[1];
    const float* bi    = (const float*)d_in[2];
    const float* Wx    = (const float*)d_in[3];
    const float* bx    = (const float*)d_in[4];
    const float* Wdt   = (const float*)d_in[5];
    const float* bdt   = (const float*)d_in[6];
    const float* A_log = (const float*)d_in[7];
    const float* Dp    = (const float*)d_in[8];
    const float* Wo    = (const float*)d_in[9];
    const float* bo    = (const float*)d_in[10];
    const float* gamma = (const float*)d_in[11];
    const float* beta  = (const float*)d_in[12];
    float* out = (float*)d_out;

    float *xs, *sres, *draw, *Bsel, *Csel, *delta, *y, *z;
    cudaGetSymbolAddress((void**)&xs,    g_xs);
    cudaGetSymbolAddress((void**)&sres,  g_sres);
    cudaGetSymbolAddress((void**)&draw,  g_draw);
    cudaGetSymbolAddress((void**)&Bsel,  g_Bsel);
    cudaGetSymbolAddress((void**)&Csel,  g_Csel);
    cudaGetSymbolAddress((void**)&delta, g_delta);
    cudaGetSymbolAddress((void**)&y,     g_y);
    cudaGetSymbolAddress((void**)&z,     g_z);

    static bool attr_done = false;
    if (!attr_done) {
        cudaFuncSetAttribute(gemm_tc<0>, cudaFuncAttributeMaxDynamicSharedMemorySize, SMEM_TC_BYTES);
        cudaFuncSetAttribute(gemm_tc<1>, cudaFuncAttributeMaxDynamicSharedMemorySize, SMEM_TC_BYTES);
        cudaFuncSetAttribute(gemm_tc<3>, cudaFuncAttributeMaxDynamicSharedMemorySize, SMEM_TC_BYTES);
        attr_done = true;
    }

    // A = -exp(A_log)
    aneg_kernel<<<(DI*DS + 255)/256, 256>>>(A_log);

    // GEMM1: x @ Wi + bi -> silu -> xs | sres
    gemm_tc<0><<<dim3(N1/128, MROWS/128), 128, SMEM_TC_BYTES>>>(
        x, Wi, bi, nullptr, xs, sres, nullptr, MROWS, N1, DM);

    // GEMM2: xs @ Wx + bx -> draw | Bsel | Csel
    gemm_tc<1><<<dim3(N2/128, MROWS/128), 128, SMEM_TC_BYTES>>>(
        xs, Wx, bx, nullptr, draw, Bsel, Csel, MROWS, N2, DI);

    // GEMM3: draw @ Wdt + bdt -> softplus -> delta  (SIMT, K=64)
    gemm_sp<<<dim3(DI/BN, MROWS/BM), 256>>>(draw, Wdt, bdt, delta, MROWS, DI, DS);

    // selective scan (fuses +xs*Dp and *silu(res))
    scan_kernel<<<(MROWS*32)/256, 256>>>(delta, Bsel, xs, Csel, sres, Dp, y);

    // GEMM4: y @ Wo + bo + residual -> z
    gemm_tc<3><<<dim3(DM/128, MROWS/128), 128, SMEM_TC_BYTES>>>(
        y, Wo, bo, x, z, nullptr, nullptr, MROWS, DM, DI);

    // layernorm -> out
    ln_kernel<<<MROWS, 256>>>(z, gamma, beta, out);
}